// round 1
// baseline (speedup 1.0000x reference)
#include <cuda_runtime.h>
#include <mma.h>
#include <math.h>

using namespace nvcuda;

#define B_  8
#define S_  1024
#define D_  2048
#define H_  16
#define DH_ 128
#define M_TOT (B_*S_)   // 8192

// Scratch (static __device__ globals: allowed; runtime allocs are not)
__device__ float g_Qp[(size_t)M_TOT * D_];            // 64 MB
__device__ float g_Kp[(size_t)M_TOT * D_];            // 64 MB
__device__ float g_Vp[(size_t)M_TOT * D_];            // 64 MB
__device__ float g_Sc[(size_t)B_ * H_ * S_ * S_];     // 512 MB

// Split a loaded fp32 fragment into tf32 hi + tf32 lo (tf32x3 emulated-fp32 MMA)
template <class Frag>
__device__ __forceinline__ void split_tf32(Frag& hi, Frag& lo) {
#pragma unroll
    for (int i = 0; i < hi.num_elements; i++) {
        float x = hi.x[i];
        float h = wmma::__float_to_tf32(x);
        hi.x[i] = h;
        lo.x[i] = wmma::__float_to_tf32(x - h);
    }
}

// ---------------------------------------------------------------------------
// Generic row-major GEMM: C[M,N] = A[M,K] @ B[K,N], batched over grid.z with
// z -> (b = z/Hdim, h = z%Hdim) pointer offsets. Block tile 128x128, BK=32,
// 256 threads = 8 warps in 4(M) x 2(N); warp tile 32x64 of m16n16k8 frags.
// tf32x3 for ~fp32 accuracy.
// ---------------------------------------------------------------------------
__global__ __launch_bounds__(256) void gemm_rr(
    const float* __restrict__ A, const float* __restrict__ Bm, float* __restrict__ C,
    int K, int ldA, int ldB, int ldC,
    long sAb, long sAh, long sBb, long sBh, long sCb, long sCh, int Hdim)
{
    int z = blockIdx.z;
    int b = z / Hdim, h = z - b * Hdim;
    A  += (long)b * sAb + (long)h * sAh;
    Bm += (long)b * sBb + (long)h * sBh;
    C  += (long)b * sCb + (long)h * sCh;

    int m0 = blockIdx.y * 128, n0 = blockIdx.x * 128;

    __shared__ __align__(128) float As[128][36];   // 128x32 tile, pad 4
    __shared__ __align__(128) float Bs[32][136];   // 32x128 tile, pad 8 (keeps float4 stores aligned)

    int tid  = threadIdx.x;
    int warp = tid >> 5;
    int wm = warp >> 1, wn = warp & 1;

    wmma::fragment<wmma::accumulator, 16, 16, 8, float> acc[2][4];
#pragma unroll
    for (int i = 0; i < 2; i++)
#pragma unroll
        for (int j = 0; j < 4; j++) wmma::fill_fragment(acc[i][j], 0.0f);

    for (int k0 = 0; k0 < K; k0 += 32) {
        // Load A tile 128x32 (1024 float4, 4 per thread)
#pragma unroll
        for (int i = 0; i < 4; i++) {
            int t4 = tid + i * 256;
            int r = t4 >> 3, c = (t4 & 7) * 4;
            float4 v = *(const float4*)(A + (long)(m0 + r) * ldA + k0 + c);
            *(float4*)&As[r][c] = v;
        }
        // Load B tile 32x128 (1024 float4)
#pragma unroll
        for (int i = 0; i < 4; i++) {
            int t4 = tid + i * 256;
            int r = t4 >> 5, c = (t4 & 31) * 4;
            float4 v = *(const float4*)(Bm + (long)(k0 + r) * ldB + n0 + c);
            *(float4*)&Bs[r][c] = v;
        }
        __syncthreads();

#pragma unroll
        for (int kk = 0; kk < 32; kk += 8) {
            wmma::fragment<wmma::matrix_a, 16, 16, 8, wmma::precision::tf32, wmma::row_major> ah[2], al[2];
            wmma::fragment<wmma::matrix_b, 16, 16, 8, wmma::precision::tf32, wmma::row_major> bh[4], bl[4];
#pragma unroll
            for (int i = 0; i < 2; i++) {
                wmma::load_matrix_sync(ah[i], &As[wm * 32 + i * 16][kk], 36);
                split_tf32(ah[i], al[i]);
            }
#pragma unroll
            for (int j = 0; j < 4; j++) {
                wmma::load_matrix_sync(bh[j], &Bs[kk][wn * 64 + j * 16], 136);
                split_tf32(bh[j], bl[j]);
            }
#pragma unroll
            for (int i = 0; i < 2; i++)
#pragma unroll
                for (int j = 0; j < 4; j++) {
                    wmma::mma_sync(acc[i][j], al[i], bh[j], acc[i][j]);
                    wmma::mma_sync(acc[i][j], ah[i], bl[j], acc[i][j]);
                    wmma::mma_sync(acc[i][j], ah[i], bh[j], acc[i][j]);
                }
        }
        __syncthreads();
    }

#pragma unroll
    for (int i = 0; i < 2; i++)
#pragma unroll
        for (int j = 0; j < 4; j++) {
            int r = m0 + wm * 32 + i * 16;
            int c = n0 + wn * 64 + j * 16;
            wmma::store_matrix_sync(C + (long)r * ldC + c, acc[i][j], ldC, wmma::mem_row_major);
        }
}

// ---------------------------------------------------------------------------
// Scores: for each (b,h): Sc = (Qh * 1/sqrt(DH)) @ Kh^T.  Qh/Kh rows have
// stride D_ inside the projected tensors. K^T handled via col_major matrix_b
// fragments over the K tile (no explicit transpose). tf32x3.
// ---------------------------------------------------------------------------
__global__ __launch_bounds__(256) void scores_kernel(
    const float* __restrict__ Qp, const float* __restrict__ Kp, float* __restrict__ Sc)
{
    int z = blockIdx.z;
    int b = z >> 4, h = z & 15;
    const float* Qh = Qp + (long)b * S_ * D_ + h * DH_;
    const float* Kh = Kp + (long)b * S_ * D_ + h * DH_;
    float* Sz = Sc + (long)z * S_ * S_;

    int m0 = blockIdx.y * 128, n0 = blockIdx.x * 128;

    __shared__ __align__(128) float Qs[128][36];
    __shared__ __align__(128) float Ks[128][36];

    const float scale = 0.088388347648318447f;  // 1/sqrt(128)

    int tid  = threadIdx.x;
    int warp = tid >> 5;
    int wm = warp >> 1, wn = warp & 1;

    wmma::fragment<wmma::accumulator, 16, 16, 8, float> acc[2][4];
#pragma unroll
    for (int i = 0; i < 2; i++)
#pragma unroll
        for (int j = 0; j < 4; j++) wmma::fill_fragment(acc[i][j], 0.0f);

    for (int k0 = 0; k0 < DH_; k0 += 32) {
#pragma unroll
        for (int i = 0; i < 4; i++) {
            int t4 = tid + i * 256;
            int r = t4 >> 3, c = (t4 & 7) * 4;
            float4 v = *(const float4*)(Qh + (long)(m0 + r) * D_ + k0 + c);
            Qs[r][c + 0] = v.x * scale;
            Qs[r][c + 1] = v.y * scale;
            Qs[r][c + 2] = v.z * scale;
            Qs[r][c + 3] = v.w * scale;
        }
#pragma unroll
        for (int i = 0; i < 4; i++) {
            int t4 = tid + i * 256;
            int r = t4 >> 3, c = (t4 & 7) * 4;
            float4 v = *(const float4*)(Kh + (long)(n0 + r) * D_ + k0 + c);
            *(float4*)&Ks[r][c] = v;
        }
        __syncthreads();

#pragma unroll
        for (int kk = 0; kk < 32; kk += 8) {
            wmma::fragment<wmma::matrix_a, 16, 16, 8, wmma::precision::tf32, wmma::row_major> ah[2], al[2];
            wmma::fragment<wmma::matrix_b, 16, 16, 8, wmma::precision::tf32, wmma::col_major> bh[4], bl[4];
#pragma unroll
            for (int i = 0; i < 2; i++) {
                wmma::load_matrix_sync(ah[i], &Qs[wm * 32 + i * 16][kk], 36);
                split_tf32(ah[i], al[i]);
            }
#pragma unroll
            for (int j = 0; j < 4; j++) {
                // col_major: element(k, jcol) = p[jcol*36 + k]  -> reads Kh rows as K^T
                wmma::load_matrix_sync(bh[j], &Ks[wn * 64 + j * 16][kk], 36);
                split_tf32(bh[j], bl[j]);
            }
#pragma unroll
            for (int i = 0; i < 2; i++)
#pragma unroll
                for (int j = 0; j < 4; j++) {
                    wmma::mma_sync(acc[i][j], al[i], bh[j], acc[i][j]);
                    wmma::mma_sync(acc[i][j], ah[i], bl[j], acc[i][j]);
                    wmma::mma_sync(acc[i][j], ah[i], bh[j], acc[i][j]);
                }
        }
        __syncthreads();
    }

#pragma unroll
    for (int i = 0; i < 2; i++)
#pragma unroll
        for (int j = 0; j < 4; j++) {
            int r = m0 + wm * 32 + i * 16;
            int c = n0 + wn * 64 + j * 16;
            wmma::store_matrix_sync(Sz + (long)r * S_ + c, acc[i][j], S_, wmma::mem_row_major);
        }
}

// ---------------------------------------------------------------------------
// Row softmax over the scores scratch (in place). One 128-thread block per row.
// ---------------------------------------------------------------------------
__global__ __launch_bounds__(128) void softmax_kernel(float* __restrict__ Sc)
{
    long row = blockIdx.x;
    float* p = Sc + row * (long)S_;
    int tid = threadIdx.x;

    float v[8];
    float mx = -1e30f;
#pragma unroll
    for (int i = 0; i < 8; i++) {
        v[i] = p[tid + i * 128];
        mx = fmaxf(mx, v[i]);
    }

    __shared__ float red[128];
    red[tid] = mx;
    __syncthreads();
#pragma unroll
    for (int s = 64; s > 0; s >>= 1) {
        if (tid < s) red[tid] = fmaxf(red[tid], red[tid + s]);
        __syncthreads();
    }
    mx = red[0];
    __syncthreads();

    float sum = 0.0f;
#pragma unroll
    for (int i = 0; i < 8; i++) {
        v[i] = __expf(v[i] - mx);
        sum += v[i];
    }
    red[tid] = sum;
    __syncthreads();
#pragma unroll
    for (int s = 64; s > 0; s >>= 1) {
        if (tid < s) red[tid] += red[tid + s];
        __syncthreads();
    }
    float inv = 1.0f / red[0];
#pragma unroll
    for (int i = 0; i < 8; i++) p[tid + i * 128] = v[i] * inv;
}

// ---------------------------------------------------------------------------
// kernel_launch: 3 projection GEMMs -> scores -> softmax -> PV (writes d_out).
// Graph-capturable: kernel launches only, no allocs, no syncs.
// ---------------------------------------------------------------------------
extern "C" void kernel_launch(void* const* d_in, const int* in_sizes, int n_in,
                              void* d_out, int out_size)
{
    (void)in_sizes; (void)n_in; (void)out_size;
    const float* q  = (const float*)d_in[0];
    const float* k  = (const float*)d_in[1];
    const float* v  = (const float*)d_in[2];
    const float* Wq = (const float*)d_in[3];
    const float* Wk = (const float*)d_in[4];
    const float* Wv = (const float*)d_in[5];
    float* out = (float*)d_out;

    float *Qp, *Kp, *Vp, *Sc;
    cudaGetSymbolAddress((void**)&Qp, g_Qp);
    cudaGetSymbolAddress((void**)&Kp, g_Kp);
    cudaGetSymbolAddress((void**)&Vp, g_Vp);
    cudaGetSymbolAddress((void**)&Sc, g_Sc);

    dim3 blk(256);

    // Projections: [8192,2048] @ [2048,2048]
    dim3 gproj(D_ / 128, M_TOT / 128, 1);
    gemm_rr<<<gproj, blk>>>(q, Wq, Qp, D_, D_, D_, D_, 0, 0, 0, 0, 0, 0, 1);
    gemm_rr<<<gproj, blk>>>(k, Wk, Kp, D_, D_, D_, D_, 0, 0, 0, 0, 0, 0, 1);
    gemm_rr<<<gproj, blk>>>(v, Wv, Vp, D_, D_, D_, D_, 0, 0, 0, 0, 0, 0, 1);

    // Scores: per (b,h) [1024,128] @ [1024,128]^T, scaled
    dim3 gsc(S_ / 128, S_ / 128, B_ * H_);
    scores_kernel<<<gsc, blk>>>(Qp, Kp, Sc);

    // Softmax over every row of scores
    softmax_kernel<<<(unsigned)((long)B_ * H_ * S_), 128>>>(Sc);

    // PV: per (b,h) [1024,1024] @ [1024,128] -> out[b, s, h*DH + d]
    dim3 gpv(1, S_ / 128, B_ * H_);
    gemm_rr<<<gpv, blk>>>(Sc, Vp, out,
                          S_,                 // K
                          S_, D_, D_,         // ldA, ldB, ldC
                          (long)H_ * S_ * S_, (long)S_ * S_,   // A z-strides (b,h)
                          (long)S_ * D_,      DH_,             // B z-strides
                          (long)S_ * D_,      DH_,             // C z-strides
                          H_);
}

// round 4
// speedup vs baseline: 3.7765x; 3.7765x over previous
#include <cuda_runtime.h>
#include <cuda_bf16.h>
#include <cstdint>

#define B_  8
#define S_  1024
#define D_  2048
#define H_  16
#define DH_ 128
#define MTOT (B_*S_)   // 8192

// ---------------------------------------------------------------------------
// Static scratch (runtime allocation forbidden). All bf16 operands are stored
// as hi/lo pairs (x = hi + lo, each bf16) for 3-pass fp32-quality MMA.
// ---------------------------------------------------------------------------
__device__ __nv_bfloat16 g_qh[(size_t)MTOT * D_], g_ql[(size_t)MTOT * D_];
__device__ __nv_bfloat16 g_kh[(size_t)MTOT * D_], g_kl[(size_t)MTOT * D_];
__device__ __nv_bfloat16 g_vh[(size_t)MTOT * D_], g_vl[(size_t)MTOT * D_];
__device__ __nv_bfloat16 g_Wqh[(size_t)D_ * D_], g_Wql[(size_t)D_ * D_];   // W^T
__device__ __nv_bfloat16 g_Wkh[(size_t)D_ * D_], g_Wkl[(size_t)D_ * D_];   // W^T
__device__ __nv_bfloat16 g_Wvh[(size_t)D_ * D_], g_Wvl[(size_t)D_ * D_];   // W^T
__device__ __nv_bfloat16 g_Qph[(size_t)MTOT * D_], g_Qpl[(size_t)MTOT * D_];
__device__ __nv_bfloat16 g_Kph[(size_t)MTOT * D_], g_Kpl[(size_t)MTOT * D_];
__device__ __nv_bfloat16 g_VTh[(size_t)D_ * MTOT], g_VTl[(size_t)D_ * MTOT]; // Vp^T
__device__ float         g_Sc[(size_t)B_ * H_ * S_ * S_];                    // 512 MB
__device__ __nv_bfloat16 g_Ph[(size_t)B_ * H_ * S_ * S_];
__device__ __nv_bfloat16 g_Pl[(size_t)B_ * H_ * S_ * S_];

// ---------------------------------------------------------------------------
// Helpers
// ---------------------------------------------------------------------------
__device__ __forceinline__ uint32_t smem_u32(const void* p) {
    uint32_t a;
    asm("{ .reg .u64 t; cvta.to.shared.u64 t, %1; cvt.u32.u64 %0, t; }" : "=r"(a) : "l"(p));
    return a;
}
__device__ __forceinline__ void split_bf16(float x, __nv_bfloat16& h, __nv_bfloat16& l) {
    h = __float2bfloat16_rn(x);
    l = __float2bfloat16_rn(x - __bfloat162float(h));
}
__device__ __forceinline__ uint32_t pack2(__nv_bfloat16 a, __nv_bfloat16 b) {
    __nv_bfloat162 t(a, b);
    return *reinterpret_cast<uint32_t*>(&t);
}

#define CP16(dst, src) asm volatile("cp.async.cg.shared.global [%0], [%1], 16;" :: "r"(dst), "l"(src))
#define CP_COMMIT()    asm volatile("cp.async.commit_group;")
#define CP_WAIT1()     asm volatile("cp.async.wait_group 1;")

#define LDSM4(r, addr)                                                          \
    asm volatile("ldmatrix.sync.aligned.m8n8.x4.shared.b16 {%0,%1,%2,%3}, [%4];" \
        : "=r"((r)[0]), "=r"((r)[1]), "=r"((r)[2]), "=r"((r)[3]) : "r"(addr))

#define MMA16816(d, a, b0, b1)                                                  \
    asm volatile("mma.sync.aligned.m16n8k16.row.col.f32.bf16.bf16.f32 "         \
        "{%0,%1,%2,%3}, {%4,%5,%6,%7}, {%8,%9}, {%0,%1,%2,%3};"                 \
        : "+f"((d)[0]), "+f"((d)[1]), "+f"((d)[2]), "+f"((d)[3])                \
        : "r"((a)[0]), "r"((a)[1]), "r"((a)[2]), "r"((a)[3]), "r"(b0), "r"(b1))

// ---------------------------------------------------------------------------
// Prep: fp32 -> hi/lo bf16 (elementwise, float4 vectorized)
// ---------------------------------------------------------------------------
__global__ __launch_bounds__(256) void conv_hl(
    const float* __restrict__ x, __nv_bfloat16* __restrict__ oh,
    __nv_bfloat16* __restrict__ ol, int n4)
{
    int i = blockIdx.x * 256 + threadIdx.x;
    if (i >= n4) return;
    float4 v = ((const float4*)x)[i];
    __nv_bfloat16 h0, h1, h2, h3, l0, l1, l2, l3;
    split_bf16(v.x, h0, l0); split_bf16(v.y, h1, l1);
    split_bf16(v.z, h2, l2); split_bf16(v.w, h3, l3);
    ((uint2*)oh)[i] = make_uint2(pack2(h0, h1), pack2(h2, h3));
    ((uint2*)ol)[i] = make_uint2(pack2(l0, l1), pack2(l2, l3));
}

// Prep: W[K,N] fp32 -> W^T[N,K] hi/lo bf16 (32x32 smem tiles)
__global__ __launch_bounds__(256) void trans_hl(
    const float* __restrict__ W, __nv_bfloat16* __restrict__ th,
    __nv_bfloat16* __restrict__ tl)
{
    __shared__ float t[32][33];
    int n0 = blockIdx.x * 32, k0 = blockIdx.y * 32;
    int tx = threadIdx.x & 31, ty = threadIdx.x >> 5;   // 32 x 8
#pragma unroll
    for (int j = 0; j < 4; ++j)
        t[ty + j * 8][tx] = W[(size_t)(k0 + ty + j * 8) * D_ + n0 + tx];
    __syncthreads();
#pragma unroll
    for (int j = 0; j < 4; ++j) {
        float v = t[tx][ty + j * 8];
        __nv_bfloat16 h, l;
        split_bf16(v, h, l);
        size_t o = (size_t)(n0 + ty + j * 8) * D_ + k0 + tx;
        th[o] = h; tl[o] = l;
    }
}

// ---------------------------------------------------------------------------
// bf16x3 GEMM: C[M,N] = alpha * A[M,K] @ B[N,K]^T  (both operands hi/lo bf16)
//   BM=128, BN=128, BK=32; 256 threads (8 warps, 2x4 grid, warp tile 64x32)
//   Double-buffered cp.async; 80B-padded smem rows (conflict-free ldmatrix).
//   EPI 0: write fp32 to Cf.  EPI 1: split alpha*acc -> Ch/Cl bf16.
//   Batched over grid.z: z -> (b = z/Hdim, h = z%Hdim) offsets.
// ---------------------------------------------------------------------------
#define ARR_B  10240          // 128 rows * 80 bytes
#define STG_B  (4 * ARR_B)    // Ah, Al, Bh, Bl
#define SMEM_TOT (2 * STG_B)  // 81920

template <int EPI>
__global__ __launch_bounds__(256) void gemm_bf16x3(
    const __nv_bfloat16* __restrict__ Ah, const __nv_bfloat16* __restrict__ Al,
    const __nv_bfloat16* __restrict__ Bh, const __nv_bfloat16* __restrict__ Bl,
    float* __restrict__ Cf, __nv_bfloat16* __restrict__ Ch, __nv_bfloat16* __restrict__ Cl,
    int K, int ldA, int ldB, int ldC,
    long sAb, long sAh_, long sBb, long sBh_, long sCb, long sCh_,
    int Hdim, float alpha)
{
    extern __shared__ char smem[];
    const uint32_t sbase = smem_u32(smem);
    const int tid = threadIdx.x, warp = tid >> 5, lane = tid & 31;

    const int z = blockIdx.z;
    const int bb = z / Hdim, hh = z - bb * Hdim;
    const long offA = (long)bb * sAb + (long)hh * sAh_;
    const long offB = (long)bb * sBb + (long)hh * sBh_;
    const long offC = (long)bb * sCb + (long)hh * sCh_;
    Ah += offA; Al += offA; Bh += offB; Bl += offB;
    // *** Round-4 fix: offset the C pointers too (this was the Round-3 bug) ***
    if (EPI == 0) { Cf += offC; } else { Ch += offC; Cl += offC; }

    const int m0 = blockIdx.y * 128, n0 = blockIdx.x * 128;
    const int wm0 = (warp >> 2) * 64, wn0 = (warp & 3) * 32;

    // per-thread load slots (2 x 16B chunks per array)
    const int cid0 = tid, cid1 = tid + 256;
    const int r0 = cid0 >> 2, ch0 = cid0 & 3;
    const int r1 = cid1 >> 2, ch1 = cid1 & 3;

    float acc[4][4][4];
#pragma unroll
    for (int i = 0; i < 4; ++i)
#pragma unroll
        for (int j = 0; j < 4; ++j)
#pragma unroll
            for (int e = 0; e < 4; ++e) acc[i][j][e] = 0.0f;

    auto load_stage = [&](int stage, int k0) {
        uint32_t base = sbase + stage * STG_B;
        const __nv_bfloat16* gp[4] = {Ah, Al, Bh, Bl};
#pragma unroll
        for (int q = 0; q < 4; ++q) {
            const __nv_bfloat16* g = gp[q];
            const int t0 = (q < 2) ? m0 : n0;
            const int ld = (q < 2) ? ldA : ldB;
            CP16(base + q * ARR_B + r0 * 80 + ch0 * 16,
                 g + (size_t)(t0 + r0) * ld + k0 + ch0 * 8);
            CP16(base + q * ARR_B + r1 * 80 + ch1 * 16,
                 g + (size_t)(t0 + r1) * ld + k0 + ch1 * 8);
        }
    };

    const int NCH = K >> 5;  // K / 32
    load_stage(0, 0);  CP_COMMIT();
    if (NCH > 1) load_stage(1, 32);
    CP_COMMIT();

    const uint32_t a_row = (uint32_t)(wm0 + (lane & 15));
    const uint32_t a_col = (uint32_t)(((lane >> 4) & 1) * 16);
    const uint32_t b_row = (uint32_t)(wn0 + (lane & 7) + ((lane >> 4) & 1) * 8);
    const uint32_t b_col = (uint32_t)(((lane >> 3) & 1) * 16);

    for (int c = 0; c < NCH; ++c) {
        CP_WAIT1();
        __syncthreads();

        const uint32_t sA_hi = sbase + (c & 1) * STG_B;
        const uint32_t sA_lo = sA_hi + ARR_B;
        const uint32_t sB_hi = sA_hi + 2 * ARR_B;
        const uint32_t sB_lo = sA_hi + 3 * ARR_B;

#pragma unroll
        for (int ks = 0; ks < 2; ++ks) {
            const uint32_t ab = a_col + ks * 32;
            const uint32_t bbyte = b_col + ks * 32;
            uint32_t ah[4][4], al[4][4], bh2[2][4], bl2[2][4];
#pragma unroll
            for (int mt = 0; mt < 4; ++mt) {
                const uint32_t ro = (a_row + mt * 16) * 80;
                LDSM4(ah[mt], sA_hi + ro + ab);
                LDSM4(al[mt], sA_lo + ro + ab);
            }
#pragma unroll
            for (int np = 0; np < 2; ++np) {
                const uint32_t ro = (b_row + np * 16) * 80;
                LDSM4(bh2[np], sB_hi + ro + bbyte);
                LDSM4(bl2[np], sB_lo + ro + bbyte);
            }
#pragma unroll
            for (int mt = 0; mt < 4; ++mt)
#pragma unroll
                for (int nt = 0; nt < 4; ++nt) {
                    const uint32_t* bh = &bh2[nt >> 1][(nt & 1) * 2];
                    const uint32_t* bl = &bl2[nt >> 1][(nt & 1) * 2];
                    MMA16816(acc[mt][nt], ah[mt], bh[0], bh[1]);  // hi*hi
                    MMA16816(acc[mt][nt], ah[mt], bl[0], bl[1]);  // hi*lo
                    MMA16816(acc[mt][nt], al[mt], bh[0], bh[1]);  // lo*hi
                }
        }
        __syncthreads();
        if (c + 2 < NCH) load_stage(c & 1, (c + 2) * 32);
        CP_COMMIT();
    }

    // Epilogue
    const int er = lane >> 2, ec = (lane & 3) * 2;
#pragma unroll
    for (int mt = 0; mt < 4; ++mt)
#pragma unroll
        for (int nt = 0; nt < 4; ++nt) {
            const int row = m0 + wm0 + mt * 16 + er;
            const int col = n0 + wn0 + nt * 8 + ec;
            float* a4 = acc[mt][nt];
            if (EPI == 0) {
                *(float2*)(Cf + (size_t)row * ldC + col)       = make_float2(a4[0], a4[1]);
                *(float2*)(Cf + (size_t)(row + 8) * ldC + col) = make_float2(a4[2], a4[3]);
            } else {
                __nv_bfloat16 h0, h1, h2, h3, l0, l1, l2, l3;
                split_bf16(a4[0] * alpha, h0, l0); split_bf16(a4[1] * alpha, h1, l1);
                split_bf16(a4[2] * alpha, h2, l2); split_bf16(a4[3] * alpha, h3, l3);
                *(uint32_t*)(Ch + (size_t)row * ldC + col)       = pack2(h0, h1);
                *(uint32_t*)(Cl + (size_t)row * ldC + col)       = pack2(l0, l1);
                *(uint32_t*)(Ch + (size_t)(row + 8) * ldC + col) = pack2(h2, h3);
                *(uint32_t*)(Cl + (size_t)(row + 8) * ldC + col) = pack2(l2, l3);
            }
        }
}

// ---------------------------------------------------------------------------
// Row softmax: read fp32 scores, write hi/lo bf16 probabilities.
// ---------------------------------------------------------------------------
__global__ __launch_bounds__(128) void softmax_kernel(
    const float* __restrict__ Sc, __nv_bfloat16* __restrict__ Ph,
    __nv_bfloat16* __restrict__ Pl)
{
    const size_t row = blockIdx.x;
    const float* p = Sc + row * (size_t)S_;
    const int tid = threadIdx.x;

    float v[8];
    float mx = -1e30f;
#pragma unroll
    for (int i = 0; i < 8; i++) { v[i] = p[tid + i * 128]; mx = fmaxf(mx, v[i]); }

    __shared__ float red[128];
    red[tid] = mx;
    __syncthreads();
#pragma unroll
    for (int s = 64; s > 0; s >>= 1) {
        if (tid < s) red[tid] = fmaxf(red[tid], red[tid + s]);
        __syncthreads();
    }
    mx = red[0];
    __syncthreads();

    float sum = 0.0f;
#pragma unroll
    for (int i = 0; i < 8; i++) { v[i] = __expf(v[i] - mx); sum += v[i]; }
    red[tid] = sum;
    __syncthreads();
#pragma unroll
    for (int s = 64; s > 0; s >>= 1) {
        if (tid < s) red[tid] += red[tid + s];
        __syncthreads();
    }
    const float inv = 1.0f / red[0];

#pragma unroll
    for (int i = 0; i < 8; i++) {
        __nv_bfloat16 h, l;
        split_bf16(v[i] * inv, h, l);
        Ph[row * S_ + tid + i * 128] = h;
        Pl[row * S_ + tid + i * 128] = l;
    }
}

// ---------------------------------------------------------------------------
// kernel_launch
// ---------------------------------------------------------------------------
extern "C" void kernel_launch(void* const* d_in, const int* in_sizes, int n_in,
                              void* d_out, int out_size)
{
    (void)in_sizes; (void)n_in; (void)out_size;
    const float* q  = (const float*)d_in[0];
    const float* k  = (const float*)d_in[1];
    const float* v  = (const float*)d_in[2];
    const float* Wq = (const float*)d_in[3];
    const float* Wk = (const float*)d_in[4];
    const float* Wv = (const float*)d_in[5];
    float* out = (float*)d_out;

    __nv_bfloat16 *qh, *ql, *kh, *kl, *vh, *vl;
    __nv_bfloat16 *Wqh, *Wql, *Wkh, *Wkl, *Wvh, *Wvl;
    __nv_bfloat16 *Qph, *Qpl, *Kph, *Kpl, *VTh, *VTl, *Ph, *Pl;
    float* Sc;
    cudaGetSymbolAddress((void**)&qh, g_qh);   cudaGetSymbolAddress((void**)&ql, g_ql);
    cudaGetSymbolAddress((void**)&kh, g_kh);   cudaGetSymbolAddress((void**)&kl, g_kl);
    cudaGetSymbolAddress((void**)&vh, g_vh);   cudaGetSymbolAddress((void**)&vl, g_vl);
    cudaGetSymbolAddress((void**)&Wqh, g_Wqh); cudaGetSymbolAddress((void**)&Wql, g_Wql);
    cudaGetSymbolAddress((void**)&Wkh, g_Wkh); cudaGetSymbolAddress((void**)&Wkl, g_Wkl);
    cudaGetSymbolAddress((void**)&Wvh, g_Wvh); cudaGetSymbolAddress((void**)&Wvl, g_Wvl);
    cudaGetSymbolAddress((void**)&Qph, g_Qph); cudaGetSymbolAddress((void**)&Qpl, g_Qpl);
    cudaGetSymbolAddress((void**)&Kph, g_Kph); cudaGetSymbolAddress((void**)&Kpl, g_Kpl);
    cudaGetSymbolAddress((void**)&VTh, g_VTh); cudaGetSymbolAddress((void**)&VTl, g_VTl);
    cudaGetSymbolAddress((void**)&Ph, g_Ph);   cudaGetSymbolAddress((void**)&Pl, g_Pl);
    cudaGetSymbolAddress((void**)&Sc, g_Sc);

    cudaFuncSetAttribute(gemm_bf16x3<0>, cudaFuncAttributeMaxDynamicSharedMemorySize, SMEM_TOT);
    cudaFuncSetAttribute(gemm_bf16x3<1>, cudaFuncAttributeMaxDynamicSharedMemorySize, SMEM_TOT);

    const float scale = 0.088388347648318447f;  // 1/sqrt(128)
    dim3 blk(256);

    // --- Prep: split inputs to hi/lo bf16; transpose weights to [N,K] ---
    const int n4 = MTOT * D_ / 4;
    conv_hl<<<n4 / 256, 256>>>(q, qh, ql, n4);
    conv_hl<<<n4 / 256, 256>>>(k, kh, kl, n4);
    conv_hl<<<n4 / 256, 256>>>(v, vh, vl, n4);
    dim3 gtr(D_ / 32, D_ / 32);
    trans_hl<<<gtr, 256>>>(Wq, Wqh, Wql);
    trans_hl<<<gtr, 256>>>(Wk, Wkh, Wkl);
    trans_hl<<<gtr, 256>>>(Wv, Wvh, Wvl);

    // --- Projections ---
    // Qp = (q @ Wq) * scale  -> hi/lo  [MTOT, D]
    dim3 gq(D_ / 128, MTOT / 128, 1);
    gemm_bf16x3<1><<<gq, blk, SMEM_TOT>>>(qh, ql, Wqh, Wql, nullptr, Qph, Qpl,
                                          D_, D_, D_, D_, 0, 0, 0, 0, 0, 0, 1, scale);
    // Kp = k @ Wk -> hi/lo
    gemm_bf16x3<1><<<gq, blk, SMEM_TOT>>>(kh, kl, Wkh, Wkl, nullptr, Kph, Kpl,
                                          D_, D_, D_, D_, 0, 0, 0, 0, 0, 0, 1, 1.0f);
    // VpT = Wv^T @ v^T: A = Wv^T [D,D], B = v [MTOT, D] -> C [D, MTOT]
    dim3 gv(MTOT / 128, D_ / 128, 1);
    gemm_bf16x3<1><<<gv, blk, SMEM_TOT>>>(Wvh, Wvl, vh, vl, nullptr, VTh, VTl,
                                          D_, D_, D_, MTOT, 0, 0, 0, 0, 0, 0, 1, 1.0f);

    // --- Scores: per (b,h)  Qp_head [S,DH] @ Kp_head [S,DH]^T -> fp32 ---
    dim3 gsc(S_ / 128, S_ / 128, B_ * H_);
    gemm_bf16x3<0><<<gsc, blk, SMEM_TOT>>>(Qph, Qpl, Kph, Kpl, Sc, nullptr, nullptr,
                                           DH_, D_, D_, S_,
                                           (long)S_ * D_, DH_,
                                           (long)S_ * D_, DH_,
                                           (long)H_ * S_ * S_, (long)S_ * S_,
                                           H_, 1.0f);

    // --- Softmax -> P hi/lo bf16 ---
    softmax_kernel<<<(unsigned)((size_t)B_ * H_ * S_), 128>>>(Sc, Ph, Pl);

    // --- PV: per (b,h)  P [S,S] @ VpT_head [DH, S]^T -> out fp32 ---
    dim3 gpv(DH_ / 128, S_ / 128, B_ * H_);
    gemm_bf16x3<0><<<gpv, blk, SMEM_TOT>>>(Ph, Pl, VTh, VTl, out, nullptr, nullptr,
                                           S_, S_, MTOT, D_,
                                           (long)H_ * S_ * S_, (long)S_ * S_,
                                           (long)S_, (long)DH_ * MTOT,
                                           (long)S_ * D_, DH_,
                                           H_, 1.0f);
}

// round 5
// speedup vs baseline: 4.0407x; 1.0700x over previous
#include <cuda_runtime.h>
#include <cuda_bf16.h>
#include <cstdint>

#define B_  8
#define S_  1024
#define D_  2048
#define H_  16
#define DH_ 128
#define MTOT (B_*S_)   // 8192

// ---------------------------------------------------------------------------
// Static scratch. All bf16 operands stored as hi/lo pairs (x = hi + lo).
// ---------------------------------------------------------------------------
__device__ __nv_bfloat16 g_qh[(size_t)MTOT * D_], g_ql[(size_t)MTOT * D_];
__device__ __nv_bfloat16 g_kh[(size_t)MTOT * D_], g_kl[(size_t)MTOT * D_];
__device__ __nv_bfloat16 g_vh[(size_t)MTOT * D_], g_vl[(size_t)MTOT * D_];
__device__ __nv_bfloat16 g_Wqh[(size_t)D_ * D_], g_Wql[(size_t)D_ * D_];   // W^T
__device__ __nv_bfloat16 g_Wkh[(size_t)D_ * D_], g_Wkl[(size_t)D_ * D_];   // W^T
__device__ __nv_bfloat16 g_Wvh[(size_t)D_ * D_], g_Wvl[(size_t)D_ * D_];   // W^T
__device__ __nv_bfloat16 g_Qph[(size_t)MTOT * D_], g_Qpl[(size_t)MTOT * D_];
__device__ __nv_bfloat16 g_Kph[(size_t)MTOT * D_], g_Kpl[(size_t)MTOT * D_];
__device__ __nv_bfloat16 g_VTh[(size_t)D_ * MTOT], g_VTl[(size_t)D_ * MTOT]; // Vp^T

// ---------------------------------------------------------------------------
// Helpers
// ---------------------------------------------------------------------------
__device__ __forceinline__ uint32_t smem_u32(const void* p) {
    uint32_t a;
    asm("{ .reg .u64 t; cvta.to.shared.u64 t, %1; cvt.u32.u64 %0, t; }" : "=r"(a) : "l"(p));
    return a;
}
__device__ __forceinline__ void split_bf16(float x, __nv_bfloat16& h, __nv_bfloat16& l) {
    h = __float2bfloat16_rn(x);
    l = __float2bfloat16_rn(x - __bfloat162float(h));
}
__device__ __forceinline__ uint32_t pack2(__nv_bfloat16 a, __nv_bfloat16 b) {
    __nv_bfloat162 t(a, b);
    return *reinterpret_cast<uint32_t*>(&t);
}
__device__ __forceinline__ void split_pack(float a, float b, uint32_t& hi, uint32_t& lo) {
    __nv_bfloat16 ha, la, hb, lb;
    split_bf16(a, ha, la); split_bf16(b, hb, lb);
    hi = pack2(ha, hb); lo = pack2(la, lb);
}
__device__ __forceinline__ float ex2f(float x) {
    float y;
    asm("ex2.approx.f32 %0, %1;" : "=f"(y) : "f"(x));
    return y;
}

#define CP16(dst, src) asm volatile("cp.async.cg.shared.global [%0], [%1], 16;" :: "r"(dst), "l"(src))
#define CP_COMMIT()    asm volatile("cp.async.commit_group;")
#define CP_WAIT1()     asm volatile("cp.async.wait_group 1;")

#define LDSM4(r, addr)                                                          \
    asm volatile("ldmatrix.sync.aligned.m8n8.x4.shared.b16 {%0,%1,%2,%3}, [%4];" \
        : "=r"((r)[0]), "=r"((r)[1]), "=r"((r)[2]), "=r"((r)[3]) : "r"(addr))

#define MMA16816(d, a, b0, b1)                                                  \
    asm volatile("mma.sync.aligned.m16n8k16.row.col.f32.bf16.bf16.f32 "         \
        "{%0,%1,%2,%3}, {%4,%5,%6,%7}, {%8,%9}, {%0,%1,%2,%3};"                 \
        : "+f"((d)[0]), "+f"((d)[1]), "+f"((d)[2]), "+f"((d)[3])                \
        : "r"((a)[0]), "r"((a)[1]), "r"((a)[2]), "r"((a)[3]), "r"(b0), "r"(b1))

// ---------------------------------------------------------------------------
// Prep kernels
// ---------------------------------------------------------------------------
__global__ __launch_bounds__(256) void conv_hl(
    const float* __restrict__ x, __nv_bfloat16* __restrict__ oh,
    __nv_bfloat16* __restrict__ ol, int n4)
{
    int i = blockIdx.x * 256 + threadIdx.x;
    if (i >= n4) return;
    float4 v = ((const float4*)x)[i];
    __nv_bfloat16 h0, h1, h2, h3, l0, l1, l2, l3;
    split_bf16(v.x, h0, l0); split_bf16(v.y, h1, l1);
    split_bf16(v.z, h2, l2); split_bf16(v.w, h3, l3);
    ((uint2*)oh)[i] = make_uint2(pack2(h0, h1), pack2(h2, h3));
    ((uint2*)ol)[i] = make_uint2(pack2(l0, l1), pack2(l2, l3));
}

__global__ __launch_bounds__(256) void trans_hl(
    const float* __restrict__ W, __nv_bfloat16* __restrict__ th,
    __nv_bfloat16* __restrict__ tl)
{
    __shared__ float t[32][33];
    int n0 = blockIdx.x * 32, k0 = blockIdx.y * 32;
    int tx = threadIdx.x & 31, ty = threadIdx.x >> 5;
#pragma unroll
    for (int j = 0; j < 4; ++j)
        t[ty + j * 8][tx] = W[(size_t)(k0 + ty + j * 8) * D_ + n0 + tx];
    __syncthreads();
#pragma unroll
    for (int j = 0; j < 4; ++j) {
        float v = t[tx][ty + j * 8];
        __nv_bfloat16 h, l;
        split_bf16(v, h, l);
        size_t o = (size_t)(n0 + ty + j * 8) * D_ + k0 + tx;
        th[o] = h; tl[o] = l;
    }
}

// ---------------------------------------------------------------------------
// bf16x3 GEMM (projections): C = alpha * A[M,K] @ B[N,K]^T -> hi/lo bf16 out
// ---------------------------------------------------------------------------
#define ARR_B  10240
#define STG_B  (4 * ARR_B)
#define SMEM_TOT (2 * STG_B)

__global__ __launch_bounds__(256) void gemm_bf16x3(
    const __nv_bfloat16* __restrict__ Ah, const __nv_bfloat16* __restrict__ Al,
    const __nv_bfloat16* __restrict__ Bh, const __nv_bfloat16* __restrict__ Bl,
    __nv_bfloat16* __restrict__ Ch, __nv_bfloat16* __restrict__ Cl,
    int K, int ldA, int ldB, int ldC, float alpha)
{
    extern __shared__ char smem[];
    const uint32_t sbase = smem_u32(smem);
    const int tid = threadIdx.x, warp = tid >> 5, lane = tid & 31;

    const int m0 = blockIdx.y * 128, n0 = blockIdx.x * 128;
    const int wm0 = (warp >> 2) * 64, wn0 = (warp & 3) * 32;

    const int r0 = tid >> 2, ch0 = tid & 3;
    const int r1 = (tid + 256) >> 2, ch1 = (tid + 256) & 3;

    float acc[4][4][4];
#pragma unroll
    for (int i = 0; i < 4; ++i)
#pragma unroll
        for (int j = 0; j < 4; ++j)
#pragma unroll
            for (int e = 0; e < 4; ++e) acc[i][j][e] = 0.0f;

    auto load_stage = [&](int stage, int k0) {
        uint32_t base = sbase + stage * STG_B;
        const __nv_bfloat16* gp[4] = {Ah, Al, Bh, Bl};
#pragma unroll
        for (int q = 0; q < 4; ++q) {
            const __nv_bfloat16* g = gp[q];
            const int t0 = (q < 2) ? m0 : n0;
            const int ld = (q < 2) ? ldA : ldB;
            CP16(base + q * ARR_B + r0 * 80 + ch0 * 16,
                 g + (size_t)(t0 + r0) * ld + k0 + ch0 * 8);
            CP16(base + q * ARR_B + r1 * 80 + ch1 * 16,
                 g + (size_t)(t0 + r1) * ld + k0 + ch1 * 8);
        }
    };

    const int NCH = K >> 5;
    load_stage(0, 0);  CP_COMMIT();
    if (NCH > 1) load_stage(1, 32);
    CP_COMMIT();

    const uint32_t a_row = (uint32_t)(wm0 + (lane & 15));
    const uint32_t a_col = (uint32_t)(((lane >> 4) & 1) * 16);
    const uint32_t b_row = (uint32_t)(wn0 + (lane & 7) + ((lane >> 4) & 1) * 8);
    const uint32_t b_col = (uint32_t)(((lane >> 3) & 1) * 16);

    for (int c = 0; c < NCH; ++c) {
        CP_WAIT1();
        __syncthreads();

        const uint32_t sA_hi = sbase + (c & 1) * STG_B;
        const uint32_t sA_lo = sA_hi + ARR_B;
        const uint32_t sB_hi = sA_hi + 2 * ARR_B;
        const uint32_t sB_lo = sA_hi + 3 * ARR_B;

#pragma unroll
        for (int ks = 0; ks < 2; ++ks) {
            const uint32_t ab = a_col + ks * 32;
            const uint32_t bbyte = b_col + ks * 32;
            uint32_t ah[4][4], al[4][4], bh2[2][4], bl2[2][4];
#pragma unroll
            for (int mt = 0; mt < 4; ++mt) {
                const uint32_t ro = (a_row + mt * 16) * 80;
                LDSM4(ah[mt], sA_hi + ro + ab);
                LDSM4(al[mt], sA_lo + ro + ab);
            }
#pragma unroll
            for (int np = 0; np < 2; ++np) {
                const uint32_t ro = (b_row + np * 16) * 80;
                LDSM4(bh2[np], sB_hi + ro + bbyte);
                LDSM4(bl2[np], sB_lo + ro + bbyte);
            }
#pragma unroll
            for (int mt = 0; mt < 4; ++mt)
#pragma unroll
                for (int nt = 0; nt < 4; ++nt) {
                    const uint32_t* bh = &bh2[nt >> 1][(nt & 1) * 2];
                    const uint32_t* bl = &bl2[nt >> 1][(nt & 1) * 2];
                    MMA16816(acc[mt][nt], ah[mt], bh[0], bh[1]);
                    MMA16816(acc[mt][nt], ah[mt], bl[0], bl[1]);
                    MMA16816(acc[mt][nt], al[mt], bh[0], bh[1]);
                }
        }
        __syncthreads();
        if (c + 2 < NCH) load_stage(c & 1, (c + 2) * 32);
        CP_COMMIT();
    }

    const int er = lane >> 2, ec = (lane & 3) * 2;
#pragma unroll
    for (int mt = 0; mt < 4; ++mt)
#pragma unroll
        for (int nt = 0; nt < 4; ++nt) {
            const int row = m0 + wm0 + mt * 16 + er;
            const int col = n0 + wn0 + nt * 8 + ec;
            float* a4 = acc[mt][nt];
            __nv_bfloat16 h0, h1, h2, h3, l0, l1, l2, l3;
            split_bf16(a4[0] * alpha, h0, l0); split_bf16(a4[1] * alpha, h1, l1);
            split_bf16(a4[2] * alpha, h2, l2); split_bf16(a4[3] * alpha, h3, l3);
            *(uint32_t*)(Ch + (size_t)row * ldC + col)       = pack2(h0, h1);
            *(uint32_t*)(Cl + (size_t)row * ldC + col)       = pack2(l0, l1);
            *(uint32_t*)(Ch + (size_t)(row + 8) * ldC + col) = pack2(h2, h3);
            *(uint32_t*)(Cl + (size_t)(row + 8) * ldC + col) = pack2(l2, l3);
        }
}

// ---------------------------------------------------------------------------
// Fused flash attention: per CTA = 128 q-rows of one (b,h).
//   Q smem 128x272B (hi+lo); K tiles 64x272B x2buf (hi+lo); V^T tiles
//   128x144B x2buf (hi+lo). Online softmax base-2 (log2e folded into Q scale).
//   S acc fragments reused directly as P A-fragments (hi/lo split in regs).
// ---------------------------------------------------------------------------
#define FQ_LO   34816u                  // Q lo offset
#define FK_OFF  69632u                  // K region
#define FV_OFF  139264u                 // V region
#define FLASH_SMEM 212992

__global__ __launch_bounds__(256) void flash_attn(
    const __nv_bfloat16* __restrict__ Qph, const __nv_bfloat16* __restrict__ Qpl,
    const __nv_bfloat16* __restrict__ Kph, const __nv_bfloat16* __restrict__ Kpl,
    const __nv_bfloat16* __restrict__ VTh, const __nv_bfloat16* __restrict__ VTl,
    float* __restrict__ out)
{
    extern __shared__ char smem[];
    const uint32_t sb = smem_u32(smem);
    const int tid = threadIdx.x, warp = tid >> 5, lane = tid & 31;
    const int q0 = blockIdx.x * 128;
    const int bh = blockIdx.y;
    const int b = bh >> 4, h = bh & 15;
    const int h128 = h * 128;

    // Q tile (hi+lo): 128 rows x 16 x 16B chunks
#pragma unroll
    for (int i = 0; i < 8; ++i) {
        int c = tid + i * 256;
        int r = c >> 4, ck = c & 15;
        size_t src = (size_t)(b * 1024 + q0 + r) * D_ + h128 + ck * 8;
        CP16(sb + r * 272 + ck * 16, Qph + src);
        CP16(sb + FQ_LO + r * 272 + ck * 16, Qpl + src);
    }

    auto load_kv = [&](int t, int buf) {
        const int k0 = t * 64;
        const uint32_t kb = sb + FK_OFF + buf * 34816;
        const uint32_t vb = sb + FV_OFF + buf * 36864;
#pragma unroll
        for (int i = 0; i < 4; ++i) {           // K: 64 rows x 16 chunks
            int c = tid + i * 256;
            int r = c >> 4, ck = c & 15;
            size_t src = (size_t)(b * 1024 + k0 + r) * D_ + h128 + ck * 8;
            CP16(kb + r * 272 + ck * 16, Kph + src);
            CP16(kb + 17408 + r * 272 + ck * 16, Kpl + src);
        }
#pragma unroll
        for (int i = 0; i < 4; ++i) {           // V^T: 128 rows x 8 chunks
            int c = tid + i * 256;
            int dr = c >> 3, ck = c & 7;
            size_t src = (size_t)(h128 + dr) * MTOT + b * 1024 + k0 + ck * 8;
            CP16(vb + dr * 144 + ck * 16, VTh + src);
            CP16(vb + 18432 + dr * 144 + ck * 16, VTl + src);
        }
    };

    load_kv(0, 0); CP_COMMIT();
    load_kv(1, 1); CP_COMMIT();

    const uint32_t aoff  = (uint32_t)((warp * 16 + (lane & 15)) * 272 + ((lane >> 4) & 1) * 16);
    const uint32_t brow  = (uint32_t)((lane & 7) + ((lane >> 4) & 1) * 8);
    const uint32_t bcolb = (uint32_t)(((lane >> 3) & 1) * 16);

    float oacc[16][4];
#pragma unroll
    for (int i = 0; i < 16; ++i)
#pragma unroll
        for (int e = 0; e < 4; ++e) oacc[i][e] = 0.0f;
    float m0 = -1e30f, m1 = -1e30f, l0 = 0.0f, l1 = 0.0f;

    for (int t = 0; t < 16; ++t) {
        CP_WAIT1();
        __syncthreads();
        const int buf = t & 1;
        const uint32_t kh_ = sb + FK_OFF + buf * 34816;
        const uint32_t kl_ = kh_ + 17408;
        const uint32_t vh_ = sb + FV_OFF + buf * 36864;
        const uint32_t vl_ = vh_ + 18432;

        // ---- S = Q . K^T  (16 q-rows x 64 keys per warp), bf16x3 ----
        float sacc[8][4];
#pragma unroll
        for (int i = 0; i < 8; ++i)
#pragma unroll
            for (int e = 0; e < 4; ++e) sacc[i][e] = 0.0f;

#pragma unroll
        for (int ks = 0; ks < 8; ++ks) {
            uint32_t qh4[4], ql4[4];
            LDSM4(qh4, sb + aoff + ks * 32);
            LDSM4(ql4, sb + FQ_LO + aoff + ks * 32);
#pragma unroll
            for (int np = 0; np < 4; ++np) {
                uint32_t kh4[4], kl4[4];
                const uint32_t off = (np * 16 + brow) * 272 + bcolb + ks * 32;
                LDSM4(kh4, kh_ + off);
                LDSM4(kl4, kl_ + off);
#pragma unroll
                for (int sub = 0; sub < 2; ++sub) {
                    float* d = sacc[np * 2 + sub];
                    MMA16816(d, qh4, kh4[sub * 2], kh4[sub * 2 + 1]);
                    MMA16816(d, qh4, kl4[sub * 2], kl4[sub * 2 + 1]);
                    MMA16816(d, ql4, kh4[sub * 2], kh4[sub * 2 + 1]);
                }
            }
        }

        // ---- online softmax (base-2; rows r=lane>>2 and r+8) ----
        float mx0 = sacc[0][0], mx1 = sacc[0][2];
#pragma unroll
        for (int nt = 0; nt < 8; ++nt) {
            mx0 = fmaxf(mx0, fmaxf(sacc[nt][0], sacc[nt][1]));
            mx1 = fmaxf(mx1, fmaxf(sacc[nt][2], sacc[nt][3]));
        }
        mx0 = fmaxf(mx0, __shfl_xor_sync(0xffffffffu, mx0, 1));
        mx0 = fmaxf(mx0, __shfl_xor_sync(0xffffffffu, mx0, 2));
        mx1 = fmaxf(mx1, __shfl_xor_sync(0xffffffffu, mx1, 1));
        mx1 = fmaxf(mx1, __shfl_xor_sync(0xffffffffu, mx1, 2));

        const float m0n = fmaxf(m0, mx0), m1n = fmaxf(m1, mx1);
        const float al0 = ex2f(m0 - m0n), al1 = ex2f(m1 - m1n);
        m0 = m0n; m1 = m1n;

#pragma unroll
        for (int nt = 0; nt < 16; ++nt) {
            oacc[nt][0] *= al0; oacc[nt][1] *= al0;
            oacc[nt][2] *= al1; oacc[nt][3] *= al1;
        }

        float s0 = 0.0f, s1 = 0.0f;
#pragma unroll
        for (int nt = 0; nt < 8; ++nt) {
            sacc[nt][0] = ex2f(sacc[nt][0] - m0);
            sacc[nt][1] = ex2f(sacc[nt][1] - m0);
            sacc[nt][2] = ex2f(sacc[nt][2] - m1);
            sacc[nt][3] = ex2f(sacc[nt][3] - m1);
            s0 += sacc[nt][0] + sacc[nt][1];
            s1 += sacc[nt][2] + sacc[nt][3];
        }
        s0 += __shfl_xor_sync(0xffffffffu, s0, 1);
        s0 += __shfl_xor_sync(0xffffffffu, s0, 2);
        s1 += __shfl_xor_sync(0xffffffffu, s1, 1);
        s1 += __shfl_xor_sync(0xffffffffu, s1, 2);
        l0 = l0 * al0 + s0;
        l1 = l1 * al1 + s1;

        // ---- O += P . V  (P frags built in regs from sacc), bf16x3 ----
#pragma unroll
        for (int kp = 0; kp < 4; ++kp) {
            uint32_t pah[4], pal[4];
            split_pack(sacc[2 * kp][0],     sacc[2 * kp][1],     pah[0], pal[0]);
            split_pack(sacc[2 * kp][2],     sacc[2 * kp][3],     pah[1], pal[1]);
            split_pack(sacc[2 * kp + 1][0], sacc[2 * kp + 1][1], pah[2], pal[2]);
            split_pack(sacc[2 * kp + 1][2], sacc[2 * kp + 1][3], pah[3], pal[3]);
#pragma unroll
            for (int np = 0; np < 8; ++np) {
                uint32_t vh4[4], vl4[4];
                const uint32_t off = (np * 16 + brow) * 144 + bcolb + kp * 32;
                LDSM4(vh4, vh_ + off);
                LDSM4(vl4, vl_ + off);
#pragma unroll
                for (int sub = 0; sub < 2; ++sub) {
                    float* d = oacc[np * 2 + sub];
                    MMA16816(d, pah, vh4[sub * 2], vh4[sub * 2 + 1]);
                    MMA16816(d, pah, vl4[sub * 2], vl4[sub * 2 + 1]);
                    MMA16816(d, pal, vh4[sub * 2], vh4[sub * 2 + 1]);
                }
            }
        }

        __syncthreads();
        if (t + 2 < 16) load_kv(t + 2, buf);
        CP_COMMIT();
    }

    // ---- finalize: O /= l, write fp32 out[b, s, h*128 + dh] ----
    const float i0 = 1.0f / l0, i1 = 1.0f / l1;
    const size_t row0 = (size_t)(b * 1024 + q0 + warp * 16 + (lane >> 2));
    const int colb = h128 + (lane & 3) * 2;
#pragma unroll
    for (int nt = 0; nt < 16; ++nt) {
        *(float2*)(out + row0 * D_ + colb + nt * 8) =
            make_float2(oacc[nt][0] * i0, oacc[nt][1] * i0);
        *(float2*)(out + (row0 + 8) * D_ + colb + nt * 8) =
            make_float2(oacc[nt][2] * i1, oacc[nt][3] * i1);
    }
}

// ---------------------------------------------------------------------------
// kernel_launch
// ---------------------------------------------------------------------------
extern "C" void kernel_launch(void* const* d_in, const int* in_sizes, int n_in,
                              void* d_out, int out_size)
{
    (void)in_sizes; (void)n_in; (void)out_size;
    const float* q  = (const float*)d_in[0];
    const float* k  = (const float*)d_in[1];
    const float* v  = (const float*)d_in[2];
    const float* Wq = (const float*)d_in[3];
    const float* Wk = (const float*)d_in[4];
    const float* Wv = (const float*)d_in[5];
    float* out = (float*)d_out;

    __nv_bfloat16 *qh, *ql, *kh, *kl, *vh, *vl;
    __nv_bfloat16 *Wqh, *Wql, *Wkh, *Wkl, *Wvh, *Wvl;
    __nv_bfloat16 *Qph, *Qpl, *Kph, *Kpl, *VTh, *VTl;
    cudaGetSymbolAddress((void**)&qh, g_qh);   cudaGetSymbolAddress((void**)&ql, g_ql);
    cudaGetSymbolAddress((void**)&kh, g_kh);   cudaGetSymbolAddress((void**)&kl, g_kl);
    cudaGetSymbolAddress((void**)&vh, g_vh);   cudaGetSymbolAddress((void**)&vl, g_vl);
    cudaGetSymbolAddress((void**)&Wqh, g_Wqh); cudaGetSymbolAddress((void**)&Wql, g_Wql);
    cudaGetSymbolAddress((void**)&Wkh, g_Wkh); cudaGetSymbolAddress((void**)&Wkl, g_Wkl);
    cudaGetSymbolAddress((void**)&Wvh, g_Wvh); cudaGetSymbolAddress((void**)&Wvl, g_Wvl);
    cudaGetSymbolAddress((void**)&Qph, g_Qph); cudaGetSymbolAddress((void**)&Qpl, g_Qpl);
    cudaGetSymbolAddress((void**)&Kph, g_Kph); cudaGetSymbolAddress((void**)&Kpl, g_Kpl);
    cudaGetSymbolAddress((void**)&VTh, g_VTh); cudaGetSymbolAddress((void**)&VTl, g_VTl);

    cudaFuncSetAttribute(gemm_bf16x3, cudaFuncAttributeMaxDynamicSharedMemorySize, SMEM_TOT);
    cudaFuncSetAttribute(flash_attn, cudaFuncAttributeMaxDynamicSharedMemorySize, FLASH_SMEM);

    // log2(e)/sqrt(DH): softmax runs in base-2 (ex2) inside flash_attn.
    const float qscale = 1.4426950408889634f * 0.0883883476483184406f;
    dim3 blk(256);

    // --- Prep ---
    const int n4 = MTOT * D_ / 4;
    conv_hl<<<n4 / 256, 256>>>(q, qh, ql, n4);
    conv_hl<<<n4 / 256, 256>>>(k, kh, kl, n4);
    conv_hl<<<n4 / 256, 256>>>(v, vh, vl, n4);
    dim3 gtr(D_ / 32, D_ / 32);
    trans_hl<<<gtr, 256>>>(Wq, Wqh, Wql);
    trans_hl<<<gtr, 256>>>(Wk, Wkh, Wkl);
    trans_hl<<<gtr, 256>>>(Wv, Wvh, Wvl);

    // --- Projections ---
    dim3 gq(D_ / 128, MTOT / 128);
    gemm_bf16x3<<<gq, blk, SMEM_TOT>>>(qh, ql, Wqh, Wql, Qph, Qpl, D_, D_, D_, D_, qscale);
    gemm_bf16x3<<<gq, blk, SMEM_TOT>>>(kh, kl, Wkh, Wkl, Kph, Kpl, D_, D_, D_, D_, 1.0f);
    dim3 gv(MTOT / 128, D_ / 128);
    gemm_bf16x3<<<gv, blk, SMEM_TOT>>>(Wvh, Wvl, vh, vl, VTh, VTl, D_, D_, D_, MTOT, 1.0f);

    // --- Fused attention ---
    dim3 gf(S_ / 128, B_ * H_);
    flash_attn<<<gf, blk, FLASH_SMEM>>>(Qph, Qpl, Kph, Kpl, VTh, VTl, out);
}